// round 13
// baseline (speedup 1.0000x reference)
#include <cuda_runtime.h>
#include <cuda_fp16.h>
#include <cstdint>

#define TDIM 1024
#define HDIM 2048
#define IDIM 5632
#define NEXP 8
#define TOPK 2
#define NROWS (TDIM * TOPK)       // 2048 routed rows
#define N1 (2 * IDIM)             // 11264 (gate+up)
#define BM 128
#define BN 128
#define BK 32
#define NSTAGE 4
#define MAXTILES 24
#define KSPLIT 2                  // GEMM2 split-K factor
#define PGRID 296                 // persistent grid: 148 SMs x 2 CTAs

#define ASTAGE 8192                         // A: 128 rows x 32 fp16, interleaved
#define BSTAGE 16384                        // B: 128 rows x 128B f32, XOR-swizzled
#define STAGE_BYTES (ASTAGE + BSTAGE)       // 24576

// ---------------- scratch (device globals: no allocations allowed) ----------
__device__ int    g_row_token[NROWS];
__device__ float  g_row_weight[NROWS];
__device__ int    g_row_slot[NROWS];
__device__ int    g_tile_expert[MAXTILES];
__device__ int    g_tile_rowstart[MAXTILES];
__device__ int    g_tile_rowcnt[MAXTILES];
__device__ int    g_ntiles;
// tile-padded, M-interleaved, k-relabeled fp16 A buffers
__device__ __half g_ax[(size_t)MAXTILES * 128 * HDIM];        // 12.6 MB
__device__ __half g_act_h[(size_t)MAXTILES * 128 * IDIM];     // 34.6 MB
__device__ float  g_partial[(size_t)KSPLIT * NROWS * HDIM];   // 32 MB

// byte offset of element (local row r, k within 32-wide kt block) in the
// interleaved A block. k relabeling pi: positions (2t,2t+1,2t+8,2t+9) hold
// original k (4t,4t+1,4t+2,4t+3).
__device__ __forceinline__ uint32_t ilv_off(int r, int kin)
{
    int ks = kin >> 4, kk = kin & 15;
    return (uint32_t)(ks * 4096 + (r >> 4) * 512 + (r & 7) * 64
         + (kk >> 2) * 16 + (((kk >> 1) & 1) * 2 + ((r >> 3) & 1)) * 4
         + (kk & 1) * 2);
}

// ---------------- routing ---------------------------------------------------
__global__ void route_kernel(const int* __restrict__ ids, const float* __restrict__ w)
{
    __shared__ int cnt[NEXP];
    __shared__ int off[NEXP];
    __shared__ int cur[NEXP];
    int tid = threadIdx.x;
    if (tid < NEXP) cnt[tid] = 0;
    __syncthreads();
    for (int a = tid; a < NROWS; a += blockDim.x)
        atomicAdd(&cnt[ids[a]], 1);
    __syncthreads();
    if (tid == 0) {
        int s = 0;
        for (int e = 0; e < NEXP; e++) { off[e] = s; cur[e] = s; s += cnt[e]; }
        int nt = 0;
        for (int e = 0; e < NEXP; e++) {
            for (int r = 0; r < cnt[e]; r += BM) {
                g_tile_expert[nt]   = e;
                g_tile_rowstart[nt] = off[e] + r;
                g_tile_rowcnt[nt]   = min(BM, cnt[e] - r);
                nt++;
            }
        }
        g_ntiles = nt;
    }
    __syncthreads();
    for (int a = tid; a < NROWS; a += blockDim.x) {
        int e = ids[a];
        int pos = atomicAdd(&cur[e], 1);
        g_row_token[pos]  = a / TOPK;
        g_row_weight[pos] = w[a];
        g_row_slot[pos]   = a;      // t*TOPK + k
    }
}

// ---------------- gather hidden -> tile-padded interleaved fp16 -------------
__global__ void gather_kernel(const float* __restrict__ src)
{
    const int tile = blockIdx.x;
    if (tile >= g_ntiles) return;
    const int r      = blockIdx.y;
    const int rowcnt = g_tile_rowcnt[tile];
    const int re     = r < rowcnt ? r : rowcnt - 1;
    const int token  = g_row_token[g_tile_rowstart[tile] + re];
    const float* srow = src + (size_t)token * HDIM;
    char* dbase = (char*)g_ax + (size_t)tile * (128 * HDIM * 2);
    const int tid = threadIdx.x;
    const int hb  = (r >> 3) & 1;
#pragma unroll
    for (int j = 0; j < 4; j++) {
        int pg  = tid + j * 256;
        int k16 = pg >> 3, p = pg & 7;
        float2 v = *(const float2*)(srow + k16 * 16 + p * 2);
        uint32_t off = (uint32_t)((k16 >> 1) * 8192 + (k16 & 1) * 4096
                     + (r >> 4) * 512 + (r & 7) * 64
                     + (p >> 1) * 16 + ((p & 1) * 2 + hb) * 4);
        *(__half2*)(dbase + off) = __floats2half2_rn(v.x, v.y);
    }
}

// ---------------- helpers ----------------------------------------------------
__device__ __forceinline__ uint32_t smem_u32(const void* p)
{
    uint32_t a;
    asm("{ .reg .u64 t; cvta.to.shared.u64 t, %1; cvt.u32.u64 %0, t; }"
        : "=r"(a) : "l"(p));
    return a;
}

__device__ __forceinline__ uint32_t packh2(float lo, float hi)
{
    uint32_t d;
    asm("cvt.rn.f16x2.f32 %0, %1, %2;" : "=r"(d) : "f"(hi), "f"(lo));
    return d;
}

#define CP_ASYNC16(dst, src) \
    asm volatile("cp.async.cg.shared.global [%0], [%1], 16;" :: "r"(dst), "l"(src) : "memory")
#define CP_COMMIT()  asm volatile("cp.async.commit_group;" ::: "memory")
#define CP_WAIT2()   asm volatile("cp.async.wait_group 2;" ::: "memory")
#define CP_WAIT0()   asm volatile("cp.async.wait_group 0;" ::: "memory")

__device__ __forceinline__ void mma_f16(float (&d)[4],
                                        const uint32_t (&a)[4],
                                        uint32_t b0, uint32_t b1)
{
    asm volatile(
        "mma.sync.aligned.m16n8k16.row.col.f32.f16.f16.f32 "
        "{%0,%1,%2,%3}, {%4,%5,%6,%7}, {%8,%9}, {%0,%1,%2,%3};\n"
        : "+f"(d[0]), "+f"(d[1]), "+f"(d[2]), "+f"(d[3])
        : "r"(a[0]), "r"(a[1]), "r"(a[2]), "r"(a[3]),
          "r"(b0), "r"(b1));
}

// ---------------- persistent grouped GEMM (fp16 mma.sync, cp.async 4-stage) -
// Work item = (tile, yblk, zblk), tile fastest. 296 CTAs loop over items.
// A: interleaved fp16 via cp.async (one contiguous 8KB block per kt).
// B: f32 natural k-order via cp.async, XOR parity swizzle (no pad).
// G2=false (GEMM1 fused SwiGLU): B rows interleave w13 gate/up; writes act.
// G2=true  (GEMM2, split-K): zblk sums K/KSPLIT slab into its own partial.
template<int KDIM, int NY, int NZ, bool G2>
__global__ void __launch_bounds__(256, 2)
moe_gemm_h(const float* __restrict__ Bsrc)
{
    extern __shared__ uint32_t dsm[];
    const uint32_t smbase = smem_u32(dsm);
    const uint32_t base   = (smbase + 127u) & ~127u;
    char* dynb            = (char*)dsm + (base - smbase);

    const int tid  = threadIdx.x;
    const int lane = tid & 31;
    const int warp = tid >> 5;
    const int wm   = (warp & 1) * 64;
    const int wn   = (warp >> 1) * 32;
    const int g    = lane >> 2;
    const int tig  = lane & 3;

    const int ntiles = g_ntiles;
    const int nitems = ntiles * NY * NZ;
    const int KITER  = (G2 ? KDIM / KSPLIT : KDIM) / BK;

    // invariant fragment/staging offsets
    const uint32_t aDst0 = (uint32_t)(tid * 16);
    const uint32_t aDst1 = (uint32_t)(4096 + tid * 16);
    const uint32_t aFB   = (uint32_t)((wm >> 4) * 512 + g * 64 + tig * 16);
    const uint32_t bRow  = (uint32_t)(ASTAGE + (wn + g) * 128);
    const uint32_t xorb  = (uint32_t)(((wn + g) & 1) << 2);
    const uint32_t bOff0 = (((uint32_t)tig) ^ xorb) * 16;
    const uint32_t bOff1 = ((4u + (uint32_t)tig) ^ xorb) * 16;

    for (int item = blockIdx.x; item < nitems; item += PGRID) {
        const int tile = item % ntiles;
        const int rest = item / ntiles;
        const int yblk = rest % NY;
        const int zblk = rest / NY;

        const int e        = g_tile_expert[tile];
        const int rowstart = g_tile_rowstart[tile];
        const int rowcnt   = g_tile_rowcnt[tile];
        const int nbase    = yblk * (G2 ? BN : 64);
        const int kbase    = G2 ? zblk * (KDIM / KSPLIT) : 0;

        // --- A staging source (cp.async block copy) ---------------------------
        const char* aBase = (G2 ? (const char*)g_act_h : (const char*)g_ax)
                          + (size_t)tile * (128 * (size_t)KDIM * 2)
                          + (size_t)kbase * 256;

        // --- B staging (coalesced cp.async, swizzled dst) ---------------------
        const int     NTOT = G2 ? HDIM : N1;
        const float*  Bexp = Bsrc + (size_t)e * NTOT * KDIM;
        const float* bSrc[4]; uint32_t bOffDst[4];
#pragma unroll
        for (int i = 0; i < 4; i++) {
            int slot = tid + 256 * i;
            int row = slot >> 3, grp = slot & 7;
            int srcrow = G2 ? (nbase + row)
                            : ((row & 1) ? IDIM : 0) + nbase + (row >> 1);
            bSrc[i]    = Bexp + (size_t)srcrow * KDIM + kbase + grp * 4;
            bOffDst[i] = (uint32_t)(ASTAGE + row * 128
                       + ((grp ^ ((row & 1) << 2)) * 16));
        }

        float acc[4][4][4];
#pragma unroll
        for (int mt = 0; mt < 4; mt++)
#pragma unroll
            for (int nt = 0; nt < 4; nt++)
#pragma unroll
                for (int i = 0; i < 4; i++) acc[mt][nt][i] = 0.f;

        // --- prologue: issue stages 0,1,2 --------------------------------------
#pragma unroll
        for (int s = 0; s < 3; s++) {
            const uint32_t sb = base + s * STAGE_BYTES;
            CP_ASYNC16(sb + aDst0, aBase + s * 8192 + aDst0);
            CP_ASYNC16(sb + aDst1, aBase + s * 8192 + aDst1);
#pragma unroll
            for (int i = 0; i < 4; i++)
                CP_ASYNC16(sb + bOffDst[i], bSrc[i] + s * BK);
            CP_COMMIT();
        }
        CP_WAIT2();            // stage 0 complete
        __syncthreads();

        int buf = 0, nxt = 3;
        for (int kt = 0; kt < KITER; kt++) {
            if (kt + 3 < KITER) {
                const uint32_t sb = base + nxt * STAGE_BYTES;
                CP_ASYNC16(sb + aDst0, aBase + (size_t)(kt + 3) * 8192 + aDst0);
                CP_ASYNC16(sb + aDst1, aBase + (size_t)(kt + 3) * 8192 + aDst1);
#pragma unroll
                for (int i = 0; i < 4; i++)
                    CP_ASYNC16(sb + bOffDst[i], bSrc[i] + (kt + 3) * BK);
            }
            CP_COMMIT();

            char* sbuf = dynb + buf * STAGE_BYTES;
#pragma unroll
            for (int ks = 0; ks < 2; ks++) {
                const char* ab = sbuf + aFB + ks * 4096;
                const char* bb = sbuf + bRow + (ks ? bOff1 : bOff0);
                uint32_t bf[4][2];
#pragma unroll
                for (int nt = 0; nt < 4; nt++) {
                    float4 v = *(const float4*)(bb + nt * 1024);   // 8 rows*128B
                    bf[nt][0] = packh2(v.x, v.y);   // positions 2tig, 2tig+1
                    bf[nt][1] = packh2(v.z, v.w);   // positions 2tig+8, 2tig+9
                }
#pragma unroll
                for (int mt = 0; mt < 4; mt++) {
                    uint4 av = *(const uint4*)(ab + mt * 512);
                    uint32_t af[4] = { av.x, av.y, av.z, av.w };
                    mma_f16(acc[mt][0], af, bf[0][0], bf[0][1]);
                    mma_f16(acc[mt][1], af, bf[1][0], bf[1][1]);
                    mma_f16(acc[mt][2], af, bf[2][0], bf[2][1]);
                    mma_f16(acc[mt][3], af, bf[3][0], bf[3][1]);
                }
            }

            CP_WAIT2();
            __syncthreads();
            buf = buf == NSTAGE - 1 ? 0 : buf + 1;
            nxt = nxt == NSTAGE - 1 ? 0 : nxt + 1;
        }

        // drain remaining cp.async groups before epilogue / next item reuse
        CP_WAIT0();
        __syncthreads();

        // --- epilogue ------------------------------------------------------------
        char* actTile = (char*)g_act_h + (size_t)tile * (128 * (size_t)IDIM * 2);
#pragma unroll
        for (int mt = 0; mt < 4; mt++) {
            int r0e = wm + mt * 16 + g;
#pragma unroll
            for (int half = 0; half < 2; half++) {
                int r = r0e + half * 8;
                if (r < rowcnt) {
                    int gr = rowstart + r;
                    if (G2) {
                        size_t cbase = (size_t)zblk * ((size_t)NROWS * HDIM)
                                     + (size_t)g_row_slot[gr] * HDIM + nbase;
                        float  wgt   = g_row_weight[gr];
#pragma unroll
                        for (int nt = 0; nt < 4; nt++) {
                            int c = wn + nt * 8 + 2 * tig;
                            float2 v;
                            v.x = acc[mt][nt][half * 2 + 0] * wgt;
                            v.y = acc[mt][nt][half * 2 + 1] * wgt;
                            *(float2*)&g_partial[cbase + c] = v;
                        }
                    } else {
                        // fused SwiGLU -> act in interleaved tile-padded layout
#pragma unroll
                        for (int nt = 0; nt < 4; nt++) {
                            float x = acc[mt][nt][half * 2 + 0];
                            float u = acc[mt][nt][half * 2 + 1];
                            float a = (x / (1.f + __expf(-x))) * u;
                            int aj = nbase + (wn >> 1) + nt * 4 + tig;
                            uint32_t off = (uint32_t)((aj >> 5) * 8192)
                                         + ilv_off(r, aj & 31);
                            *(__half*)(actTile + off) = __float2half_rn(a);
                        }
                    }
                }
            }
        }
        __syncthreads();   // smem stages reused by next item
    }
}

// ---------------- combine (atomic-free, deterministic) ----------------------
__global__ void combine_kernel(float* __restrict__ out)
{
    size_t idx = (size_t)blockIdx.x * blockDim.x + threadIdx.x;   // T*H
    size_t t = idx / HDIM;
    const size_t SP = (size_t)NROWS * HDIM;
    size_t b0 = idx + t * HDIM;          // slot 2t
    float s = g_partial[b0] + g_partial[b0 + HDIM]
            + g_partial[SP + b0] + g_partial[SP + b0 + HDIM];
    out[idx] = s;
}

// ---------------- launch -----------------------------------------------------
extern "C" void kernel_launch(void* const* d_in, const int* in_sizes, int n_in,
                              void* d_out, int out_size)
{
    const float* hidden = (const float*)d_in[0];
    const int*   ids    = (const int*)d_in[1];
    const float* wts    = (const float*)d_in[2];
    // d_in[3] = router_logits (unused)
    const float* w13    = (const float*)d_in[4];
    const float* w2     = (const float*)d_in[5];
    float* out = (float*)d_out;

    const int smem_bytes = 128 + NSTAGE * STAGE_BYTES;   // 98432
    cudaFuncSetAttribute(moe_gemm_h<HDIM, IDIM / 64, 1, false>,
                         cudaFuncAttributeMaxDynamicSharedMemorySize, smem_bytes);
    cudaFuncSetAttribute(moe_gemm_h<IDIM, HDIM / BN, KSPLIT, true>,
                         cudaFuncAttributeMaxDynamicSharedMemorySize, smem_bytes);

    route_kernel<<<1, 256>>>(ids, wts);
    gather_kernel<<<dim3(MAXTILES, 128), 256>>>(hidden);

    // GEMM1 (fused SwiGLU), persistent: items = ntiles * 88
    moe_gemm_h<HDIM, IDIM / 64, 1, false>
        <<<PGRID, 256, smem_bytes>>>(w13);

    // GEMM2 (split-K=2), persistent: items = ntiles * 16 * 2
    moe_gemm_h<IDIM, HDIM / BN, KSPLIT, true>
        <<<PGRID, 256, smem_bytes>>>(w2);

    combine_kernel<<<(int)(((size_t)TDIM * HDIM) / 256), 256>>>(out);
}

// round 14
// speedup vs baseline: 1.0554x; 1.0554x over previous
#include <cuda_runtime.h>
#include <cuda_fp16.h>
#include <cstdint>

#define TDIM 1024
#define HDIM 2048
#define IDIM 5632
#define NEXP 8
#define TOPK 2
#define NROWS (TDIM * TOPK)       // 2048 routed rows
#define N1 (2 * IDIM)             // 11264 (gate+up)
#define BM 128
#define BN 128
#define BK 32
#define NSTAGE 4
#define MAXTILES 24
#define KSPLIT 2                  // GEMM2 split-K factor

#define ASTAGE 8192                         // A: 128 rows x 32 fp16, interleaved
#define BSTAGE 16384                        // B: 128 rows x 128B f32, XOR-swizzled
#define STAGE_BYTES (ASTAGE + BSTAGE)       // 24576

// ---------------- scratch (device globals: no allocations allowed) ----------
__device__ int    g_row_token[NROWS];
__device__ float  g_row_weight[NROWS];
__device__ int    g_row_slot[NROWS];
__device__ int    g_tile_expert[MAXTILES];
__device__ int    g_tile_rowstart[MAXTILES];
__device__ int    g_tile_rowcnt[MAXTILES];
__device__ int    g_ntiles;
// tile-padded, M-interleaved, k-relabeled fp16 A buffers
__device__ __half g_ax[(size_t)MAXTILES * 128 * HDIM];        // 12.6 MB
__device__ __half g_act_h[(size_t)MAXTILES * 128 * IDIM];     // 34.6 MB
__device__ float  g_partial[(size_t)KSPLIT * NROWS * HDIM];   // 32 MB

// byte offset of element (local row r, k within 32-wide kt block) in the
// interleaved A block. k relabeling pi: positions (2t,2t+1,2t+8,2t+9) hold
// original k (4t,4t+1,4t+2,4t+3).
__device__ __forceinline__ uint32_t ilv_off(int r, int kin)
{
    int ks = kin >> 4, kk = kin & 15;
    return (uint32_t)(ks * 4096 + (r >> 4) * 512 + (r & 7) * 64
         + (kk >> 2) * 16 + (((kk >> 1) & 1) * 2 + ((r >> 3) & 1)) * 4
         + (kk & 1) * 2);
}

// ---------------- routing ---------------------------------------------------
__global__ void route_kernel(const int* __restrict__ ids, const float* __restrict__ w)
{
    __shared__ int cnt[NEXP];
    __shared__ int off[NEXP];
    __shared__ int cur[NEXP];
    int tid = threadIdx.x;
    if (tid < NEXP) cnt[tid] = 0;
    __syncthreads();
    for (int a = tid; a < NROWS; a += blockDim.x)
        atomicAdd(&cnt[ids[a]], 1);
    __syncthreads();
    if (tid == 0) {
        int s = 0;
        for (int e = 0; e < NEXP; e++) { off[e] = s; cur[e] = s; s += cnt[e]; }
        int nt = 0;
        for (int e = 0; e < NEXP; e++) {
            for (int r = 0; r < cnt[e]; r += BM) {
                g_tile_expert[nt]   = e;
                g_tile_rowstart[nt] = off[e] + r;
                g_tile_rowcnt[nt]   = min(BM, cnt[e] - r);
                nt++;
            }
        }
        g_ntiles = nt;
    }
    __syncthreads();
    for (int a = tid; a < NROWS; a += blockDim.x) {
        int e = ids[a];
        int pos = atomicAdd(&cur[e], 1);
        g_row_token[pos]  = a / TOPK;
        g_row_weight[pos] = w[a];
        g_row_slot[pos]   = a;      // t*TOPK + k
    }
}

// ---------------- gather hidden -> tile-padded interleaved fp16 -------------
__global__ void gather_kernel(const float* __restrict__ src)
{
    const int tile = blockIdx.x;
    if (tile >= g_ntiles) return;
    const int r      = blockIdx.y;
    const int rowcnt = g_tile_rowcnt[tile];
    const int re     = r < rowcnt ? r : rowcnt - 1;
    const int token  = g_row_token[g_tile_rowstart[tile] + re];
    const float* srow = src + (size_t)token * HDIM;
    char* dbase = (char*)g_ax + (size_t)tile * (128 * HDIM * 2);
    const int tid = threadIdx.x;
    const int hb  = (r >> 3) & 1;
#pragma unroll
    for (int j = 0; j < 4; j++) {
        int pg  = tid + j * 256;
        int k16 = pg >> 3, p = pg & 7;
        float2 v = *(const float2*)(srow + k16 * 16 + p * 2);
        uint32_t off = (uint32_t)((k16 >> 1) * 8192 + (k16 & 1) * 4096
                     + (r >> 4) * 512 + (r & 7) * 64
                     + (p >> 1) * 16 + ((p & 1) * 2 + hb) * 4);
        *(__half2*)(dbase + off) = __floats2half2_rn(v.x, v.y);
    }
}

// ---------------- helpers ----------------------------------------------------
__device__ __forceinline__ uint32_t smem_u32(const void* p)
{
    uint32_t a;
    asm("{ .reg .u64 t; cvta.to.shared.u64 t, %1; cvt.u32.u64 %0, t; }"
        : "=r"(a) : "l"(p));
    return a;
}

__device__ __forceinline__ uint32_t packh2(float lo, float hi)
{
    uint32_t d;
    asm("cvt.rn.f16x2.f32 %0, %1, %2;" : "=r"(d) : "f"(hi), "f"(lo));
    return d;
}

#define CP_ASYNC16(dst, src) \
    asm volatile("cp.async.cg.shared.global [%0], [%1], 16;" :: "r"(dst), "l"(src) : "memory")
#define CP_COMMIT()  asm volatile("cp.async.commit_group;" ::: "memory")
#define CP_WAIT2()   asm volatile("cp.async.wait_group 2;" ::: "memory")

__device__ __forceinline__ void mma_f16(float (&d)[4],
                                        const uint32_t (&a)[4],
                                        uint32_t b0, uint32_t b1)
{
    asm volatile(
        "mma.sync.aligned.m16n8k16.row.col.f32.f16.f16.f32 "
        "{%0,%1,%2,%3}, {%4,%5,%6,%7}, {%8,%9}, {%0,%1,%2,%3};\n"
        : "+f"(d[0]), "+f"(d[1]), "+f"(d[2]), "+f"(d[3])
        : "r"(a[0]), "r"(a[1]), "r"(a[2]), "r"(a[3]),
          "r"(b0), "r"(b1));
}

// ---------------- grouped GEMM (fp16 mma.sync + cp.async 4-stage, paired) ---
// A: interleaved fp16 via cp.async (one contiguous 8KB block per kt).
// B: f32 natural k-order via cp.async, XOR parity swizzle (no pad).
// Mainloop consumes TWO k-tiles per barrier round: issue kt+2,kt+3 ->
// wait_group 2 -> sync -> consume kt,kt+1 (64 MMAs barrier-free) -> sync.
// G2=false (GEMM1 fused SwiGLU): B rows interleave w13 gate/up; writes act.
// G2=true  (GEMM2, split-K): z-block sums K/KSPLIT slab into its own partial.
template<int KDIM, bool G2>
__global__ void __launch_bounds__(256, 2)
moe_gemm_h(const float* __restrict__ Bsrc)
{
    const int tile = blockIdx.x;
    if (tile >= g_ntiles) return;
    const int e        = g_tile_expert[tile];
    const int rowstart = g_tile_rowstart[tile];
    const int rowcnt   = g_tile_rowcnt[tile];
    const int nbase    = blockIdx.y * (G2 ? BN : 64);
    const int KLOC     = G2 ? KDIM / KSPLIT : KDIM;
    const int kbase    = G2 ? blockIdx.z * KLOC : 0;

    extern __shared__ uint32_t dsm[];
    const uint32_t smbase = smem_u32(dsm);
    const uint32_t base   = (smbase + 127u) & ~127u;
    char* dynb            = (char*)dsm + (base - smbase);

    const int tid  = threadIdx.x;
    const int lane = tid & 31;
    const int warp = tid >> 5;
    const int wm   = (warp & 1) * 64;
    const int wn   = (warp >> 1) * 32;
    const int g    = lane >> 2;
    const int tig  = lane & 3;

    // --- A staging source (cp.async block copy) -------------------------------
    const char* aBase = (G2 ? (const char*)g_act_h : (const char*)g_ax)
                      + (size_t)tile * (128 * (size_t)KDIM * 2)
                      + (size_t)kbase * 256;
    const uint32_t aDst0 = (uint32_t)(tid * 16);
    const uint32_t aDst1 = (uint32_t)(4096 + tid * 16);

    // --- B staging (coalesced cp.async, natural k order, swizzled dst) --------
    const int     NTOT = G2 ? HDIM : N1;
    const float*  Bexp = Bsrc + (size_t)e * NTOT * KDIM;
    const float* bSrc[4]; uint32_t bOffDst[4];
#pragma unroll
    for (int i = 0; i < 4; i++) {
        int slot = tid + 256 * i;
        int row = slot >> 3, grp = slot & 7;
        int srcrow = G2 ? (nbase + row)
                        : ((row & 1) ? IDIM : 0) + nbase + (row >> 1);
        bSrc[i]    = Bexp + (size_t)srcrow * KDIM + kbase + grp * 4;
        bOffDst[i] = (uint32_t)(ASTAGE + row * 128
                   + ((grp ^ ((row & 1) << 2)) * 16));
    }

    float acc[4][4][4];
#pragma unroll
    for (int mt = 0; mt < 4; mt++)
#pragma unroll
        for (int nt = 0; nt < 4; nt++)
#pragma unroll
            for (int i = 0; i < 4; i++) acc[mt][nt][i] = 0.f;

    const int KITER = KLOC / BK;    // even (64 or 88)

    // --- prologue: issue stages 0,1 ---------------------------------------------
#pragma unroll
    for (int s = 0; s < 2; s++) {
        const uint32_t sb = base + s * STAGE_BYTES;
        CP_ASYNC16(sb + aDst0, aBase + s * 8192 + aDst0);
        CP_ASYNC16(sb + aDst1, aBase + s * 8192 + aDst1);
#pragma unroll
        for (int i = 0; i < 4; i++)
            CP_ASYNC16(sb + bOffDst[i], bSrc[i] + s * BK);
        CP_COMMIT();
    }

    // fragment base offsets (within stage)
    const uint32_t aFB  = (uint32_t)((wm >> 4) * 512 + g * 64 + tig * 16);
    const uint32_t bRow = (uint32_t)(ASTAGE + (wn + g) * 128);
    const uint32_t xorb = (uint32_t)(((wn + g) & 1) << 2);
    const uint32_t bOff0 = (((uint32_t)tig) ^ xorb) * 16;
    const uint32_t bOff1 = ((4u + (uint32_t)tig) ^ xorb) * 16;

    int buf = 0;   // slot of stage kt
    for (int kt = 0; kt < KITER; kt += 2) {
        // issue stages kt+2, kt+3 into slots buf+2, buf+3 (consumed a full
        // pair ago, behind that pair's trailing barrier)
#pragma unroll
        for (int j = 0; j < 2; j++) {
            if (kt + 2 + j < KITER) {
                const int s  = (buf + 2 + j) & 3;
                const uint32_t sb = base + s * STAGE_BYTES;
                CP_ASYNC16(sb + aDst0, aBase + (size_t)(kt + 2 + j) * 8192 + aDst0);
                CP_ASYNC16(sb + aDst1, aBase + (size_t)(kt + 2 + j) * 8192 + aDst1);
#pragma unroll
                for (int i = 0; i < 4; i++)
                    CP_ASYNC16(sb + bOffDst[i], bSrc[i] + (kt + 2 + j) * BK);
            }
            CP_COMMIT();
        }
        CP_WAIT2();        // stages kt, kt+1 complete (pending: kt+2, kt+3)
        __syncthreads();   // all warps' copies visible

        // consume stages kt (slot buf) and kt+1 (slot buf+1) barrier-free
#pragma unroll
        for (int half = 0; half < 2; half++) {
            char* sbuf = dynb + ((buf + half) & 3) * STAGE_BYTES;
#pragma unroll
            for (int ks = 0; ks < 2; ks++) {
                const char* ab = sbuf + aFB + ks * 4096;
                const char* bb = sbuf + bRow + (ks ? bOff1 : bOff0);
                uint32_t bf[4][2];
#pragma unroll
                for (int nt = 0; nt < 4; nt++) {
                    float4 v = *(const float4*)(bb + nt * 1024);   // 8 rows*128B
                    bf[nt][0] = packh2(v.x, v.y);   // positions 2tig, 2tig+1
                    bf[nt][1] = packh2(v.z, v.w);   // positions 2tig+8, 2tig+9
                }
#pragma unroll
                for (int mt = 0; mt < 4; mt++) {
                    uint4 av = *(const uint4*)(ab + mt * 512);
                    uint32_t af[4] = { av.x, av.y, av.z, av.w };
                    mma_f16(acc[mt][0], af, bf[0][0], bf[0][1]);
                    mma_f16(acc[mt][1], af, bf[1][0], bf[1][1]);
                    mma_f16(acc[mt][2], af, bf[2][0], bf[2][1]);
                    mma_f16(acc[mt][3], af, bf[3][0], bf[3][1]);
                }
            }
        }

        __syncthreads();   // slots buf, buf+1 free for reuse next pair
        buf = (buf + 2) & 3;
    }

    // --- epilogue ----------------------------------------------------------------
    char* actTile = (char*)g_act_h + (size_t)tile * (128 * (size_t)IDIM * 2);
#pragma unroll
    for (int mt = 0; mt < 4; mt++) {
        int r0e = wm + mt * 16 + g;
#pragma unroll
        for (int half = 0; half < 2; half++) {
            int r = r0e + half * 8;
            if (r < rowcnt) {
                int gr = rowstart + r;
                if (G2) {
                    size_t cbase = (size_t)blockIdx.z * ((size_t)NROWS * HDIM)
                                 + (size_t)g_row_slot[gr] * HDIM + nbase;
                    float  wgt   = g_row_weight[gr];
#pragma unroll
                    for (int nt = 0; nt < 4; nt++) {
                        int c = wn + nt * 8 + 2 * tig;
                        float2 v;
                        v.x = acc[mt][nt][half * 2 + 0] * wgt;
                        v.y = acc[mt][nt][half * 2 + 1] * wgt;
                        *(float2*)&g_partial[cbase + c] = v;
                    }
                } else {
                    // fused SwiGLU -> act in interleaved tile-padded layout
#pragma unroll
                    for (int nt = 0; nt < 4; nt++) {
                        float x = acc[mt][nt][half * 2 + 0];
                        float u = acc[mt][nt][half * 2 + 1];
                        float a = (x / (1.f + __expf(-x))) * u;
                        int aj = nbase + (wn >> 1) + nt * 4 + tig;
                        uint32_t off = (uint32_t)((aj >> 5) * 8192)
                                     + ilv_off(r, aj & 31);
                        *(__half*)(actTile + off) = __float2half_rn(a);
                    }
                }
            }
        }
    }
}

// ---------------- combine (atomic-free, deterministic) ----------------------
__global__ void combine_kernel(float* __restrict__ out)
{
    size_t idx = (size_t)blockIdx.x * blockDim.x + threadIdx.x;   // T*H
    size_t t = idx / HDIM;
    const size_t SP = (size_t)NROWS * HDIM;
    size_t b0 = idx + t * HDIM;          // slot 2t
    float s = g_partial[b0] + g_partial[b0 + HDIM]
            + g_partial[SP + b0] + g_partial[SP + b0 + HDIM];
    out[idx] = s;
}

// ---------------- launch -----------------------------------------------------
extern "C" void kernel_launch(void* const* d_in, const int* in_sizes, int n_in,
                              void* d_out, int out_size)
{
    const float* hidden = (const float*)d_in[0];
    const int*   ids    = (const int*)d_in[1];
    const float* wts    = (const float*)d_in[2];
    // d_in[3] = router_logits (unused)
    const float* w13    = (const float*)d_in[4];
    const float* w2     = (const float*)d_in[5];
    float* out = (float*)d_out;

    const int smem_bytes = 128 + NSTAGE * STAGE_BYTES;   // 98432
    cudaFuncSetAttribute(moe_gemm_h<HDIM, false>,
                         cudaFuncAttributeMaxDynamicSharedMemorySize, smem_bytes);
    cudaFuncSetAttribute(moe_gemm_h<IDIM, true>,
                         cudaFuncAttributeMaxDynamicSharedMemorySize, smem_bytes);

    route_kernel<<<1, 256>>>(ids, wts);
    gather_kernel<<<dim3(MAXTILES, 128), 256>>>(hidden);

    // GEMM1 (fused SwiGLU): each y-block produces 64 act columns
    moe_gemm_h<HDIM, false>
        <<<dim3(MAXTILES, IDIM / 64), 256, smem_bytes>>>(w13);

    // GEMM2: split-K=2 over z for wave balance
    moe_gemm_h<IDIM, true>
        <<<dim3(MAXTILES, HDIM / BN, KSPLIT), 256, smem_bytes>>>(w2);

    combine_kernel<<<(int)(((size_t)TDIM * HDIM) / 256), 256>>>(out);
}

// round 15
// speedup vs baseline: 1.0639x; 1.0081x over previous
#include <cuda_runtime.h>
#include <cuda_fp16.h>
#include <cstdint>

#define TDIM 1024
#define HDIM 2048
#define IDIM 5632
#define NEXP 8
#define TOPK 2
#define NROWS (TDIM * TOPK)       // 2048 routed rows
#define N1 (2 * IDIM)             // 11264 (gate+up)
#define BM 128
#define BN 128
#define BK 32
#define NSTAGE 4
#define MAXTILES 24
#define KSPLIT 2                  // GEMM2 split-K factor

#define ASTAGE 8192                         // A: 128 rows x 32 fp16, interleaved
#define BSTAGE 16384                        // B: 128 rows x 128B f32, XOR-swizzled
#define STAGE_BYTES (ASTAGE + BSTAGE)       // 24576

// ---------------- scratch (device globals: no allocations allowed) ----------
__device__ int    g_row_token[NROWS];
__device__ float  g_row_weight[NROWS];
__device__ int    g_row_slot[NROWS];
__device__ int    g_tile_expert[MAXTILES];
__device__ int    g_tile_rowstart[MAXTILES];
__device__ int    g_tile_rowcnt[MAXTILES];
__device__ int    g_ntiles;
// tile-padded, M-interleaved, k-relabeled fp16 A buffers
__device__ __half g_ax[(size_t)MAXTILES * 128 * HDIM];        // 12.6 MB
__device__ __half g_act_h[(size_t)MAXTILES * 128 * IDIM];     // 34.6 MB
__device__ float  g_partial[(size_t)KSPLIT * NROWS * HDIM];   // 32 MB

// byte offset of element (local row r, k within 32-wide kt block) in the
// interleaved A block. k relabeling pi: positions (2t,2t+1,2t+8,2t+9) hold
// original k (4t,4t+1,4t+2,4t+3).
__device__ __forceinline__ uint32_t ilv_off(int r, int kin)
{
    int ks = kin >> 4, kk = kin & 15;
    return (uint32_t)(ks * 4096 + (r >> 4) * 512 + (r & 7) * 64
         + (kk >> 2) * 16 + (((kk >> 1) & 1) * 2 + ((r >> 3) & 1)) * 4
         + (kk & 1) * 2);
}

// ---------------- routing ---------------------------------------------------
__global__ void route_kernel(const int* __restrict__ ids, const float* __restrict__ w)
{
    __shared__ int cnt[NEXP];
    __shared__ int off[NEXP];
    __shared__ int cur[NEXP];
    int tid = threadIdx.x;
    if (tid < NEXP) cnt[tid] = 0;
    __syncthreads();
    for (int a = tid; a < NROWS; a += blockDim.x)
        atomicAdd(&cnt[ids[a]], 1);
    __syncthreads();
    if (tid == 0) {
        int s = 0;
        for (int e = 0; e < NEXP; e++) { off[e] = s; cur[e] = s; s += cnt[e]; }
        int nt = 0;
        for (int e = 0; e < NEXP; e++) {
            for (int r = 0; r < cnt[e]; r += BM) {
                g_tile_expert[nt]   = e;
                g_tile_rowstart[nt] = off[e] + r;
                g_tile_rowcnt[nt]   = min(BM, cnt[e] - r);
                nt++;
            }
        }
        g_ntiles = nt;
    }
    __syncthreads();
    for (int a = tid; a < NROWS; a += blockDim.x) {
        int e = ids[a];
        int pos = atomicAdd(&cur[e], 1);
        g_row_token[pos]  = a / TOPK;
        g_row_weight[pos] = w[a];
        g_row_slot[pos]   = a;      // t*TOPK + k
    }
}

// ---------------- gather hidden -> tile-padded interleaved fp16 -------------
// One LDG.128 covers pairs (p, p+1) of a k16 group; their half2 destinations
// live 8B apart in the same 16B chunk of the interleaved layout.
__global__ void gather_kernel(const float* __restrict__ src)
{
    const int tile = blockIdx.x;
    if (tile >= g_ntiles) return;
    const int r      = blockIdx.y;
    const int rowcnt = g_tile_rowcnt[tile];
    const int re     = r < rowcnt ? r : rowcnt - 1;
    const int token  = g_row_token[g_tile_rowstart[tile] + re];
    const float* srow = src + (size_t)token * HDIM;
    char* dbase = (char*)g_ax + (size_t)tile * (128 * HDIM * 2);
    const int tid = threadIdx.x;
    const int hb  = (r >> 3) & 1;
#pragma unroll
    for (int j = 0; j < 2; j++) {
        int qg  = tid + j * 256;            // quad index 0..511 (2 pairs each)
        int k16 = qg >> 2, pq = qg & 3;     // pq = pair-pair index (p = 2*pq)
        float4 v = *(const float4*)(srow + k16 * 16 + pq * 4);
        uint32_t chunk = (uint32_t)((k16 >> 1) * 8192 + (k16 & 1) * 4096
                       + (r >> 4) * 512 + (r & 7) * 64 + pq * 16);
        // pair p=2*pq (even): slot (0+hb)*4 ; pair p+1 (odd): slot (2+hb)*4
        *(__half2*)(dbase + chunk + (uint32_t)hb * 4)     = __floats2half2_rn(v.x, v.y);
        *(__half2*)(dbase + chunk + 8 + (uint32_t)hb * 4) = __floats2half2_rn(v.z, v.w);
    }
}

// ---------------- helpers ----------------------------------------------------
__device__ __forceinline__ uint32_t smem_u32(const void* p)
{
    uint32_t a;
    asm("{ .reg .u64 t; cvta.to.shared.u64 t, %1; cvt.u32.u64 %0, t; }"
        : "=r"(a) : "l"(p));
    return a;
}

__device__ __forceinline__ uint32_t packh2(float lo, float hi)
{
    uint32_t d;
    asm("cvt.rn.f16x2.f32 %0, %1, %2;" : "=r"(d) : "f"(hi), "f"(lo));
    return d;
}

#define CP_ASYNC16(dst, src) \
    asm volatile("cp.async.cg.shared.global [%0], [%1], 16;" :: "r"(dst), "l"(src) : "memory")
#define CP_COMMIT()  asm volatile("cp.async.commit_group;" ::: "memory")
#define CP_WAIT2()   asm volatile("cp.async.wait_group 2;" ::: "memory")

__device__ __forceinline__ void mma_f16(float (&d)[4],
                                        const uint32_t (&a)[4],
                                        uint32_t b0, uint32_t b1)
{
    asm volatile(
        "mma.sync.aligned.m16n8k16.row.col.f32.f16.f16.f32 "
        "{%0,%1,%2,%3}, {%4,%5,%6,%7}, {%8,%9}, {%0,%1,%2,%3};\n"
        : "+f"(d[0]), "+f"(d[1]), "+f"(d[2]), "+f"(d[3])
        : "r"(a[0]), "r"(a[1]), "r"(a[2]), "r"(a[3]),
          "r"(b0), "r"(b1));
}

// ---------------- grouped GEMM (fp16 mma.sync + cp.async 4-stage) -----------
// A: interleaved fp16 via cp.async (one contiguous 8KB block per kt).
// B: f32 natural k-order via cp.async, XOR parity swizzle (no pad):
//    chunk grp of row stored at slot grp ^ ((row&1)<<2) -> store and LDS.128
//    consumer phases both conflict-free at 128B rows.
// G2=false (GEMM1 fused SwiGLU): B rows interleave w13 gate/up; writes act.
// G2=true  (GEMM2, split-K): z-block sums K/KSPLIT slab into its own partial.
template<int KDIM, bool G2>
__global__ void __launch_bounds__(256, 2)
moe_gemm_h(const float* __restrict__ Bsrc)
{
    const int tile = blockIdx.x;
    if (tile >= g_ntiles) return;
    const int e        = g_tile_expert[tile];
    const int rowstart = g_tile_rowstart[tile];
    const int rowcnt   = g_tile_rowcnt[tile];
    const int nbase    = blockIdx.y * (G2 ? BN : 64);
    const int KLOC     = G2 ? KDIM / KSPLIT : KDIM;
    const int kbase    = G2 ? blockIdx.z * KLOC : 0;

    extern __shared__ uint32_t dsm[];
    const uint32_t smbase = smem_u32(dsm);
    const uint32_t base   = (smbase + 127u) & ~127u;
    char* dynb            = (char*)dsm + (base - smbase);

    const int tid  = threadIdx.x;
    const int lane = tid & 31;
    const int warp = tid >> 5;
    const int wm   = (warp & 1) * 64;
    const int wn   = (warp >> 1) * 32;
    const int g    = lane >> 2;
    const int tig  = lane & 3;

    // --- A staging source (cp.async block copy) -------------------------------
    const char* aBase = (G2 ? (const char*)g_act_h : (const char*)g_ax)
                      + (size_t)tile * (128 * (size_t)KDIM * 2)
                      + (size_t)kbase * 256;
    const uint32_t aDst0 = (uint32_t)(tid * 16);
    const uint32_t aDst1 = (uint32_t)(4096 + tid * 16);

    // --- B staging (coalesced cp.async, natural k order, swizzled dst) --------
    const int     NTOT = G2 ? HDIM : N1;
    const float*  Bexp = Bsrc + (size_t)e * NTOT * KDIM;
    const float* bSrc[4]; uint32_t bOffDst[4];
#pragma unroll
    for (int i = 0; i < 4; i++) {
        int slot = tid + 256 * i;
        int row = slot >> 3, grp = slot & 7;
        int srcrow = G2 ? (nbase + row)
                        : ((row & 1) ? IDIM : 0) + nbase + (row >> 1);
        bSrc[i]    = Bexp + (size_t)srcrow * KDIM + kbase + grp * 4;
        bOffDst[i] = (uint32_t)(ASTAGE + row * 128
                   + ((grp ^ ((row & 1) << 2)) * 16));
    }

    float acc[4][4][4];
#pragma unroll
    for (int mt = 0; mt < 4; mt++)
#pragma unroll
        for (int nt = 0; nt < 4; nt++)
#pragma unroll
            for (int i = 0; i < 4; i++) acc[mt][nt][i] = 0.f;

    const int KITER = KLOC / BK;

    // --- prologue: issue stages 0,1,2 ------------------------------------------
#pragma unroll
    for (int s = 0; s < 3; s++) {
        const uint32_t sb = base + s * STAGE_BYTES;
        CP_ASYNC16(sb + aDst0, aBase + s * 8192 + aDst0);
        CP_ASYNC16(sb + aDst1, aBase + s * 8192 + aDst1);
#pragma unroll
        for (int i = 0; i < 4; i++)
            CP_ASYNC16(sb + bOffDst[i], bSrc[i] + s * BK);
        CP_COMMIT();
    }
    CP_WAIT2();            // stage 0 complete
    __syncthreads();

    // fragment base offsets (within stage)
    const uint32_t aFB  = (uint32_t)((wm >> 4) * 512 + g * 64 + tig * 16);
    const uint32_t bRow = (uint32_t)(ASTAGE + (wn + g) * 128);
    const uint32_t xorb = (uint32_t)(((wn + g) & 1) << 2);
    // per-ks chunk byte offsets within the row
    const uint32_t bOff0 = ((0 * 4 + (uint32_t)tig) ^ xorb) * 16;
    const uint32_t bOff1 = ((1 * 4 + (uint32_t)tig) ^ xorb) * 16;

    int buf = 0, nxt = 3;
    for (int kt = 0; kt < KITER; kt++) {
        if (kt + 3 < KITER) {
            const uint32_t sb = base + nxt * STAGE_BYTES;
            CP_ASYNC16(sb + aDst0, aBase + (size_t)(kt + 3) * 8192 + aDst0);
            CP_ASYNC16(sb + aDst1, aBase + (size_t)(kt + 3) * 8192 + aDst1);
#pragma unroll
            for (int i = 0; i < 4; i++)
                CP_ASYNC16(sb + bOffDst[i], bSrc[i] + (kt + 3) * BK);
        }
        CP_COMMIT();

        char* sbuf = dynb + buf * STAGE_BYTES;
#pragma unroll
        for (int ks = 0; ks < 2; ks++) {
            const char* ab = sbuf + aFB + ks * 4096;
            const char* bb = sbuf + bRow + (ks ? bOff1 : bOff0);
            uint32_t bf[4][2];
#pragma unroll
            for (int nt = 0; nt < 4; nt++) {
                float4 v = *(const float4*)(bb + nt * 1024);   // 8 rows * 128B
                bf[nt][0] = packh2(v.x, v.y);   // positions 2tig, 2tig+1
                bf[nt][1] = packh2(v.z, v.w);   // positions 2tig+8, 2tig+9
            }
#pragma unroll
            for (int mt = 0; mt < 4; mt++) {
                uint4 av = *(const uint4*)(ab + mt * 512);
                uint32_t af[4] = { av.x, av.y, av.z, av.w };
                mma_f16(acc[mt][0], af, bf[0][0], bf[0][1]);
                mma_f16(acc[mt][1], af, bf[1][0], bf[1][1]);
                mma_f16(acc[mt][2], af, bf[2][0], bf[2][1]);
                mma_f16(acc[mt][3], af, bf[3][0], bf[3][1]);
            }
        }

        CP_WAIT2();
        __syncthreads();
        buf = buf == NSTAGE - 1 ? 0 : buf + 1;
        nxt = nxt == NSTAGE - 1 ? 0 : nxt + 1;
    }

    // --- epilogue ----------------------------------------------------------------
    char* actTile = (char*)g_act_h + (size_t)tile * (128 * (size_t)IDIM * 2);
#pragma unroll
    for (int mt = 0; mt < 4; mt++) {
        int r0e = wm + mt * 16 + g;
#pragma unroll
        for (int half = 0; half < 2; half++) {
            int r = r0e + half * 8;
            if (r < rowcnt) {
                int gr = rowstart + r;
                if (G2) {
                    size_t cbase = (size_t)blockIdx.z * ((size_t)NROWS * HDIM)
                                 + (size_t)g_row_slot[gr] * HDIM + nbase;
                    float  wgt   = g_row_weight[gr];
#pragma unroll
                    for (int nt = 0; nt < 4; nt++) {
                        int c = wn + nt * 8 + 2 * tig;
                        float2 v;
                        v.x = acc[mt][nt][half * 2 + 0] * wgt;
                        v.y = acc[mt][nt][half * 2 + 1] * wgt;
                        *(float2*)&g_partial[cbase + c] = v;
                    }
                } else {
                    // fused SwiGLU -> act in interleaved tile-padded layout
#pragma unroll
                    for (int nt = 0; nt < 4; nt++) {
                        float x = acc[mt][nt][half * 2 + 0];
                        float u = acc[mt][nt][half * 2 + 1];
                        float a = (x / (1.f + __expf(-x))) * u;
                        int aj = nbase + (wn >> 1) + nt * 4 + tig;
                        uint32_t off = (uint32_t)((aj >> 5) * 8192)
                                     + ilv_off(r, aj & 31);
                        *(__half*)(actTile + off) = __float2half_rn(a);
                    }
                }
            }
        }
    }
}

// ---------------- combine (atomic-free, deterministic, float4) --------------
__global__ void combine_kernel(float* __restrict__ out)
{
    size_t q = (size_t)blockIdx.x * blockDim.x + threadIdx.x;   // quad index, T*H/4
    size_t idx = q * 4;
    size_t t = idx / HDIM;
    const size_t SP = (size_t)NROWS * HDIM;
    size_t b0 = idx + t * HDIM;          // slot 2t base
    float4 p0 = *(const float4*)&g_partial[b0];
    float4 p1 = *(const float4*)&g_partial[b0 + HDIM];
    float4 p2 = *(const float4*)&g_partial[SP + b0];
    float4 p3 = *(const float4*)&g_partial[SP + b0 + HDIM];
    float4 s;
    s.x = p0.x + p1.x + p2.x + p3.x;
    s.y = p0.y + p1.y + p2.y + p3.y;
    s.z = p0.z + p1.z + p2.z + p3.z;
    s.w = p0.w + p1.w + p2.w + p3.w;
    *(float4*)&out[idx] = s;
}

// ---------------- launch -----------------------------------------------------
extern "C" void kernel_launch(void* const* d_in, const int* in_sizes, int n_in,
                              void* d_out, int out_size)
{
    const float* hidden = (const float*)d_in[0];
    const int*   ids    = (const int*)d_in[1];
    const float* wts    = (const float*)d_in[2];
    // d_in[3] = router_logits (unused)
    const float* w13    = (const float*)d_in[4];
    const float* w2     = (const float*)d_in[5];
    float* out = (float*)d_out;

    const int smem_bytes = 128 + NSTAGE * STAGE_BYTES;   // 98432
    cudaFuncSetAttribute(moe_gemm_h<HDIM, false>,
                         cudaFuncAttributeMaxDynamicSharedMemorySize, smem_bytes);
    cudaFuncSetAttribute(moe_gemm_h<IDIM, true>,
                         cudaFuncAttributeMaxDynamicSharedMemorySize, smem_bytes);

    route_kernel<<<1, 256>>>(ids, wts);
    gather_kernel<<<dim3(MAXTILES, 128), 256>>>(hidden);

    // GEMM1 (fused SwiGLU): each y-block produces 64 act columns
    moe_gemm_h<HDIM, false>
        <<<dim3(MAXTILES, IDIM / 64), 256, smem_bytes>>>(w13);

    // GEMM2: split-K=2 over z for wave balance
    moe_gemm_h<IDIM, true>
        <<<dim3(MAXTILES, HDIM / BN, KSPLIT), 256, smem_bytes>>>(w2);

    combine_kernel<<<(int)(((size_t)TDIM * HDIM) / 1024), 256>>>(out);
}

// round 16
// speedup vs baseline: 1.0743x; 1.0097x over previous
#include <cuda_runtime.h>
#include <cuda_fp16.h>
#include <cstdint>

#define TDIM 1024
#define HDIM 2048
#define IDIM 5632
#define NEXP 8
#define TOPK 2
#define NROWS (TDIM * TOPK)       // 2048 routed rows
#define N1 (2 * IDIM)             // 11264 (gate+up)
#define BM 128
#define BN 128
#define BK 32
#define NSTAGE 4
#define MAXTILES 24
#define KSPLIT 2                  // GEMM2 split-K factor

#define ASTAGE 8192                         // A: 128 rows x 32 fp16, interleaved
#define BSTAGE 16384                        // B: 128 rows x 128B f32, XOR-swizzled
#define STAGE_BYTES (ASTAGE + BSTAGE)       // 24576

// ---------------- scratch (device globals: no allocations allowed) ----------
__device__ int    g_row_token[NROWS];
__device__ float  g_row_weight[NROWS];
__device__ int    g_row_slot[NROWS];
__device__ int    g_tile_expert[MAXTILES];
__device__ int    g_tile_rowstart[MAXTILES];
__device__ int    g_tile_rowcnt[MAXTILES];
__device__ int    g_ntiles;
// tile-padded, M-interleaved, k-relabeled fp16 A buffers
__device__ __half g_ax[(size_t)MAXTILES * 128 * HDIM];        // 12.6 MB
__device__ __half g_act_h[(size_t)MAXTILES * 128 * IDIM];     // 34.6 MB
__device__ float  g_partial[(size_t)KSPLIT * NROWS * HDIM];   // 32 MB

// byte offset of element (local row r, k within 32-wide kt block) in the
// interleaved A block. k relabeling pi: positions (2t,2t+1,2t+8,2t+9) hold
// original k (4t,4t+1,4t+2,4t+3).
__device__ __forceinline__ uint32_t ilv_off(int r, int kin)
{
    int ks = kin >> 4, kk = kin & 15;
    return (uint32_t)(ks * 4096 + (r >> 4) * 512 + (r & 7) * 64
         + (kk >> 2) * 16 + (((kk >> 1) & 1) * 2 + ((r >> 3) & 1)) * 4
         + (kk & 1) * 2);
}

// ---------------- routing ---------------------------------------------------
__global__ void route_kernel(const int* __restrict__ ids, const float* __restrict__ w)
{
    __shared__ int cnt[NEXP];
    __shared__ int off[NEXP];
    __shared__ int cur[NEXP];
    int tid = threadIdx.x;
    if (tid < NEXP) cnt[tid] = 0;
    __syncthreads();
    for (int a = tid; a < NROWS; a += blockDim.x)
        atomicAdd(&cnt[ids[a]], 1);
    __syncthreads();
    if (tid == 0) {
        int s = 0;
        for (int e = 0; e < NEXP; e++) { off[e] = s; cur[e] = s; s += cnt[e]; }
        int nt = 0;
        for (int e = 0; e < NEXP; e++) {
            for (int r = 0; r < cnt[e]; r += BM) {
                g_tile_expert[nt]   = e;
                g_tile_rowstart[nt] = off[e] + r;
                g_tile_rowcnt[nt]   = min(BM, cnt[e] - r);
                nt++;
            }
        }
        g_ntiles = nt;
    }
    __syncthreads();
    for (int a = tid; a < NROWS; a += blockDim.x) {
        int e = ids[a];
        int pos = atomicAdd(&cur[e], 1);
        g_row_token[pos]  = a / TOPK;
        g_row_weight[pos] = w[a];
        g_row_slot[pos]   = a;      // t*TOPK + k
    }
}

// ---------------- gather hidden -> tile-padded interleaved fp16 -------------
__global__ void gather_kernel(const float* __restrict__ src)
{
    const int tile = blockIdx.x;
    if (tile >= g_ntiles) return;
    const int r      = blockIdx.y;
    const int rowcnt = g_tile_rowcnt[tile];
    const int re     = r < rowcnt ? r : rowcnt - 1;
    const int token  = g_row_token[g_tile_rowstart[tile] + re];
    const float* srow = src + (size_t)token * HDIM;
    char* dbase = (char*)g_ax + (size_t)tile * (128 * HDIM * 2);
    const int tid = threadIdx.x;
    const int hb  = (r >> 3) & 1;
#pragma unroll
    for (int j = 0; j < 2; j++) {
        int qg  = tid + j * 256;            // quad index 0..511 (2 pairs each)
        int k16 = qg >> 2, pq = qg & 3;
        float4 v = *(const float4*)(srow + k16 * 16 + pq * 4);
        uint32_t chunk = (uint32_t)((k16 >> 1) * 8192 + (k16 & 1) * 4096
                       + (r >> 4) * 512 + (r & 7) * 64 + pq * 16);
        *(__half2*)(dbase + chunk + (uint32_t)hb * 4)     = __floats2half2_rn(v.x, v.y);
        *(__half2*)(dbase + chunk + 8 + (uint32_t)hb * 4) = __floats2half2_rn(v.z, v.w);
    }
}

// ---------------- helpers ----------------------------------------------------
__device__ __forceinline__ uint32_t smem_u32(const void* p)
{
    uint32_t a;
    asm("{ .reg .u64 t; cvta.to.shared.u64 t, %1; cvt.u32.u64 %0, t; }"
        : "=r"(a) : "l"(p));
    return a;
}

__device__ __forceinline__ uint32_t packh2(float lo, float hi)
{
    uint32_t d;
    asm("cvt.rn.f16x2.f32 %0, %1, %2;" : "=r"(d) : "f"(hi), "f"(lo));
    return d;
}

#define CP_ASYNC16(dst, src) \
    asm volatile("cp.async.cg.shared.global [%0], [%1], 16;" :: "r"(dst), "l"(src) : "memory")
#define CP_COMMIT()  asm volatile("cp.async.commit_group;" ::: "memory")
#define CP_WAIT0()   asm volatile("cp.async.wait_group 0;" ::: "memory")

__device__ __forceinline__ void mma_f16(float (&d)[4],
                                        const uint32_t (&a)[4],
                                        uint32_t b0, uint32_t b1)
{
    asm volatile(
        "mma.sync.aligned.m16n8k16.row.col.f32.f16.f16.f32 "
        "{%0,%1,%2,%3}, {%4,%5,%6,%7}, {%8,%9}, {%0,%1,%2,%3};\n"
        : "+f"(d[0]), "+f"(d[1]), "+f"(d[2]), "+f"(d[3])
        : "r"(a[0]), "r"(a[1]), "r"(a[2]), "r"(a[3]),
          "r"(b0), "r"(b1));
}

// ---------------- grouped GEMM (fp16 mma.sync, 1 sync per 2 k-tiles) --------
// A: interleaved fp16 via cp.async (one contiguous 8KB block per kt).
// B: f32 natural k-order via cp.async, XOR parity swizzle (no pad).
// Paired mainloop, ONE wait + ONE barrier per 2 kt:
//   pair p: wait_group 0 (pair p data) -> sync -> issue pair p+1 into the
//   slots consumed during pair p-1 (freed by this same barrier) -> consume
//   pair p's 2 k-tiles (64 MMAs) barrier-free.
// G2=false (GEMM1 fused SwiGLU): B rows interleave w13 gate/up; writes act.
// G2=true  (GEMM2, split-K): z-block sums K/KSPLIT slab into its own partial.
template<int KDIM, bool G2>
__global__ void __launch_bounds__(256, 2)
moe_gemm_h(const float* __restrict__ Bsrc)
{
    const int tile = blockIdx.x;
    if (tile >= g_ntiles) return;
    const int e        = g_tile_expert[tile];
    const int rowstart = g_tile_rowstart[tile];
    const int rowcnt   = g_tile_rowcnt[tile];
    const int nbase    = blockIdx.y * (G2 ? BN : 64);
    const int KLOC     = G2 ? KDIM / KSPLIT : KDIM;
    const int kbase    = G2 ? blockIdx.z * KLOC : 0;

    extern __shared__ uint32_t dsm[];
    const uint32_t smbase = smem_u32(dsm);
    const uint32_t base   = (smbase + 127u) & ~127u;
    char* dynb            = (char*)dsm + (base - smbase);

    const int tid  = threadIdx.x;
    const int lane = tid & 31;
    const int warp = tid >> 5;
    const int wm   = (warp & 1) * 64;
    const int wn   = (warp >> 1) * 32;
    const int g    = lane >> 2;
    const int tig  = lane & 3;

    // --- A staging source (cp.async block copy) -------------------------------
    const char* aBase = (G2 ? (const char*)g_act_h : (const char*)g_ax)
                      + (size_t)tile * (128 * (size_t)KDIM * 2)
                      + (size_t)kbase * 256;
    const uint32_t aDst0 = (uint32_t)(tid * 16);
    const uint32_t aDst1 = (uint32_t)(4096 + tid * 16);

    // --- B staging (coalesced cp.async, natural k order, swizzled dst) --------
    const int     NTOT = G2 ? HDIM : N1;
    const float*  Bexp = Bsrc + (size_t)e * NTOT * KDIM;
    const float* bSrc[4]; uint32_t bOffDst[4];
#pragma unroll
    for (int i = 0; i < 4; i++) {
        int slot = tid + 256 * i;
        int row = slot >> 3, grp = slot & 7;
        int srcrow = G2 ? (nbase + row)
                        : ((row & 1) ? IDIM : 0) + nbase + (row >> 1);
        bSrc[i]    = Bexp + (size_t)srcrow * KDIM + kbase + grp * 4;
        bOffDst[i] = (uint32_t)(ASTAGE + row * 128
                   + ((grp ^ ((row & 1) << 2)) * 16));
    }

    float acc[4][4][4];
#pragma unroll
    for (int mt = 0; mt < 4; mt++)
#pragma unroll
        for (int nt = 0; nt < 4; nt++)
#pragma unroll
            for (int i = 0; i < 4; i++) acc[mt][nt][i] = 0.f;

    const int KITER = KLOC / BK;    // even (64 or 88)

    // --- prologue: issue pair 0 (stages 0,1 -> slots 0,1) -----------------------
#pragma unroll
    for (int s = 0; s < 2; s++) {
        const uint32_t sb = base + s * STAGE_BYTES;
        CP_ASYNC16(sb + aDst0, aBase + s * 8192 + aDst0);
        CP_ASYNC16(sb + aDst1, aBase + s * 8192 + aDst1);
#pragma unroll
        for (int i = 0; i < 4; i++)
            CP_ASYNC16(sb + bOffDst[i], bSrc[i] + s * BK);
        CP_COMMIT();
    }

    // fragment base offsets (within stage)
    const uint32_t aFB  = (uint32_t)((wm >> 4) * 512 + g * 64 + tig * 16);
    const uint32_t bRow = (uint32_t)(ASTAGE + (wn + g) * 128);
    const uint32_t xorb = (uint32_t)(((wn + g) & 1) << 2);
    const uint32_t bOff0 = (((uint32_t)tig) ^ xorb) * 16;
    const uint32_t bOff1 = ((4u + (uint32_t)tig) ^ xorb) * 16;

    int buf = 0;   // slot base of current pair (0 or 2)
    for (int kt = 0; kt < KITER; kt += 2) {
        CP_WAIT0();        // this pair's copies complete (nothing else pending)
        __syncthreads();   // publish to all warps; frees pair p-1's slots

        // issue pair p+1 into the other slot pair (freed by the barrier above)
#pragma unroll
        for (int j = 0; j < 2; j++) {
            if (kt + 2 + j < KITER) {
                const int s = (buf ^ 2) + j;
                const uint32_t sb = base + s * STAGE_BYTES;
                CP_ASYNC16(sb + aDst0, aBase + (size_t)(kt + 2 + j) * 8192 + aDst0);
                CP_ASYNC16(sb + aDst1, aBase + (size_t)(kt + 2 + j) * 8192 + aDst1);
#pragma unroll
                for (int i = 0; i < 4; i++)
                    CP_ASYNC16(sb + bOffDst[i], bSrc[i] + (kt + 2 + j) * BK);
            }
            CP_COMMIT();
        }

        // consume pair p: slots buf, buf+1 — barrier-free 64-MMA run
#pragma unroll
        for (int half = 0; half < 2; half++) {
            char* sbuf = dynb + (buf + half) * STAGE_BYTES;
#pragma unroll
            for (int ks = 0; ks < 2; ks++) {
                const char* ab = sbuf + aFB + ks * 4096;
                const char* bb = sbuf + bRow + (ks ? bOff1 : bOff0);
                uint32_t bf[4][2];
#pragma unroll
                for (int nt = 0; nt < 4; nt++) {
                    float4 v = *(const float4*)(bb + nt * 1024);   // 8 rows*128B
                    bf[nt][0] = packh2(v.x, v.y);   // positions 2tig, 2tig+1
                    bf[nt][1] = packh2(v.z, v.w);   // positions 2tig+8, 2tig+9
                }
#pragma unroll
                for (int mt = 0; mt < 4; mt++) {
                    uint4 av = *(const uint4*)(ab + mt * 512);
                    uint32_t af[4] = { av.x, av.y, av.z, av.w };
                    mma_f16(acc[mt][0], af, bf[0][0], bf[0][1]);
                    mma_f16(acc[mt][1], af, bf[1][0], bf[1][1]);
                    mma_f16(acc[mt][2], af, bf[2][0], bf[2][1]);
                    mma_f16(acc[mt][3], af, bf[3][0], bf[3][1]);
                }
            }
        }

        buf ^= 2;
    }

    // --- epilogue ----------------------------------------------------------------
    char* actTile = (char*)g_act_h + (size_t)tile * (128 * (size_t)IDIM * 2);
#pragma unroll
    for (int mt = 0; mt < 4; mt++) {
        int r0e = wm + mt * 16 + g;
#pragma unroll
        for (int half = 0; half < 2; half++) {
            int r = r0e + half * 8;
            if (r < rowcnt) {
                int gr = rowstart + r;
                if (G2) {
                    size_t cbase = (size_t)blockIdx.z * ((size_t)NROWS * HDIM)
                                 + (size_t)g_row_slot[gr] * HDIM + nbase;
                    float  wgt   = g_row_weight[gr];
#pragma unroll
                    for (int nt = 0; nt < 4; nt++) {
                        int c = wn + nt * 8 + 2 * tig;
                        float2 v;
                        v.x = acc[mt][nt][half * 2 + 0] * wgt;
                        v.y = acc[mt][nt][half * 2 + 1] * wgt;
                        *(float2*)&g_partial[cbase + c] = v;
                    }
                } else {
                    // fused SwiGLU -> act in interleaved tile-padded layout
#pragma unroll
                    for (int nt = 0; nt < 4; nt++) {
                        float x = acc[mt][nt][half * 2 + 0];
                        float u = acc[mt][nt][half * 2 + 1];
                        float a = (x / (1.f + __expf(-x))) * u;
                        int aj = nbase + (wn >> 1) + nt * 4 + tig;
                        uint32_t off = (uint32_t)((aj >> 5) * 8192)
                                     + ilv_off(r, aj & 31);
                        *(__half*)(actTile + off) = __float2half_rn(a);
                    }
                }
            }
        }
    }
}

// ---------------- combine (atomic-free, deterministic, float4) --------------
__global__ void combine_kernel(float* __restrict__ out)
{
    size_t q = (size_t)blockIdx.x * blockDim.x + threadIdx.x;   // quad index
    size_t idx = q * 4;
    size_t t = idx / HDIM;
    const size_t SP = (size_t)NROWS * HDIM;
    size_t b0 = idx + t * HDIM;          // slot 2t base
    float4 p0 = *(const float4*)&g_partial[b0];
    float4 p1 = *(const float4*)&g_partial[b0 + HDIM];
    float4 p2 = *(const float4*)&g_partial[SP + b0];
    float4 p3 = *(const float4*)&g_partial[SP + b0 + HDIM];
    float4 s;
    s.x = p0.x + p1.x + p2.x + p3.x;
    s.y = p0.y + p1.y + p2.y + p3.y;
    s.z = p0.z + p1.z + p2.z + p3.z;
    s.w = p0.w + p1.w + p2.w + p3.w;
    *(float4*)&out[idx] = s;
}

// ---------------- launch -----------------------------------------------------
extern "C" void kernel_launch(void* const* d_in, const int* in_sizes, int n_in,
                              void* d_out, int out_size)
{
    const float* hidden = (const float*)d_in[0];
    const int*   ids    = (const int*)d_in[1];
    const float* wts    = (const float*)d_in[2];
    // d_in[3] = router_logits (unused)
    const float* w13    = (const float*)d_in[4];
    const float* w2     = (const float*)d_in[5];
    float* out = (float*)d_out;

    const int smem_bytes = 128 + NSTAGE * STAGE_BYTES;   // 98432
    cudaFuncSetAttribute(moe_gemm_h<HDIM, false>,
                         cudaFuncAttributeMaxDynamicSharedMemorySize, smem_bytes);
    cudaFuncSetAttribute(moe_gemm_h<IDIM, true>,
                         cudaFuncAttributeMaxDynamicSharedMemorySize, smem_bytes);

    route_kernel<<<1, 256>>>(ids, wts);
    gather_kernel<<<dim3(MAXTILES, 128), 256>>>(hidden);

    // GEMM1 (fused SwiGLU): each y-block produces 64 act columns
    moe_gemm_h<HDIM, false>
        <<<dim3(MAXTILES, IDIM / 64), 256, smem_bytes>>>(w13);

    // GEMM2: split-K=2 over z for wave balance
    moe_gemm_h<IDIM, true>
        <<<dim3(MAXTILES, HDIM / BN, KSPLIT), 256, smem_bytes>>>(w2);

    combine_kernel<<<(int)(((size_t)TDIM * HDIM) / 1024), 256>>>(out);
}